// round 14
// baseline (speedup 1.0000x reference)
#include <cuda_runtime.h>
#include <math.h>
#include <stdint.h>

#define GSZ 32
#define LL  1024
#define BB  4
#define NNB 20
#define BP  (BB*NNB)     // 80
#define CC  128
#define HW  256
#define NRAY 360
#define NI   384

// packed f32x2 FMA (Blackwell): one inst = 2 fp32 FMAs
#define FMA_F32X2(d,a,b,c) asm("fma.rn.f32x2 %0, %1, %2, %3;" : "=l"(d) : "l"(a), "l"(b), "l"(c))
// cp.async 16B global->shared (L1 bypass)
#define CP16(dst, src) asm volatile("cp.async.cg.shared.global [%0], [%1], 16;" :: "r"(dst), "l"(src))
#define CP_COMMIT()    asm volatile("cp.async.commit_group;")
#define CP_WAIT_ALL()  asm volatile("cp.async.wait_group 0;")

__device__ __forceinline__ uint32_t smem_u32(const void* p) {
    uint32_t a;
    asm("{ .reg .u64 t; cvta.to.shared.u64 t, %1; cvt.u32.u64 %0, t; }" : "=r"(a) : "l"(p));
    return a;
}

// ---------------- scratch (device globals; no allocations) ----------------
__device__ float g_eR [NRAY*HW];
__device__ float g_eRT[HW*NI];            // [hw][ind], cols 360..383 stay zero
__device__ float g_eP [BP*HW];
__device__ float g_ePT[HW*BP];            // [hw][bp]
__device__ float g_BT [(size_t)BP*HW*CC]; // [bp][k][f] = feats*eP transposed
__device__ float g_T  [NI*BP];            // [ind][bp], rows >=360 garbage (never read)
__device__ float g_G[(size_t)BP*NRAY*CC]; // 14.7 MB
__device__ int   g_ind[BB*LL*NNB];
__device__ float g_eD [BB*LL*NNB];
__device__ float g_invZ[BB*LL];

// ---------------- merged R/P tables: circular convs + fused exp ------------
__global__ void k_RP(const float* __restrict__ rays, const float* __restrict__ feats,
                     const float* __restrict__ w1, const float* __restrict__ w2,
                     const float* __restrict__ fw) {
    __shared__ float sbuf[3*HW];
    __shared__ float sw1[27], sw2[75];
    int t = threadIdx.x;
    int y = t >> 5, x = t & 31;

    if (blockIdx.x < NRAY) {
        int ind = blockIdx.x;
        for (int i = t; i < 3*HW; i += 256) sbuf[i] = rays[(size_t)ind*3*HW + i];
        if (t < 27) sw1[t] = w1[9  + t];   // conv1 channels 1..3
        if (t < 75) sw2[t] = w2[25 + t];   // conv2 channels 1..3
        __syncthreads();
        float a1 = 0.f, a2 = 0.f;
        #pragma unroll
        for (int c = 0; c < 3; c++) {
            const float* rc = sbuf + c*HW;
            #pragma unroll
            for (int ky = 0; ky < 3; ky++) {
                int yy = ((y + ky + 7) & 7) * 32;
                #pragma unroll
                for (int kx = 0; kx < 3; kx++)
                    a1 = fmaf(sw1[c*9 + ky*3 + kx], rc[yy + ((x + kx + 31) & 31)], a1);
            }
            #pragma unroll
            for (int ky = 0; ky < 5; ky++) {
                int yy = ((y + ky + 6) & 7) * 32;
                #pragma unroll
                for (int kx = 0; kx < 5; kx++)
                    a2 = fmaf(sw2[c*25 + ky*5 + kx], rc[yy + ((x + kx + 30) & 31)], a2);
            }
        }
        float e = expf(fw[0]*a1 + fw[1]*a2);
        g_eR [ind*HW + t]  = e;
        g_eRT[t*NI + ind]  = e;
    } else {
        int bp = blockIdx.x - NRAY;
        {
            const float* base = feats + (size_t)bp*CC*HW + t;
            float mx = -3.4e38f, sm = 0.f;
            #pragma unroll 8
            for (int c = 0; c < CC; c++) {
                float v = base[(size_t)c*HW];
                mx = fmaxf(mx, v);
                sm += v;
            }
            sbuf[t]      = mx;
            sbuf[HW + t] = sm * (1.0f/128.0f);
        }
        if (t < 18) sw1[t] = w1[4*9  + t];  // conv1 channels 4..5
        if (t < 50) sw2[t] = w2[4*25 + t];  // conv2 channels 4..5
        __syncthreads();
        float a1 = 0.f, a2 = 0.f;
        #pragma unroll
        for (int m = 0; m < 2; m++) {
            const float* pc = sbuf + m*HW;
            #pragma unroll
            for (int ky = 0; ky < 3; ky++) {
                int yy = ((y + ky + 7) & 7) * 32;
                #pragma unroll
                for (int kx = 0; kx < 3; kx++)
                    a1 = fmaf(sw1[m*9 + ky*3 + kx], pc[yy + ((x + kx + 31) & 31)], a1);
            }
            #pragma unroll
            for (int ky = 0; ky < 5; ky++) {
                int yy = ((y + ky + 6) & 7) * 32;
                #pragma unroll
                for (int kx = 0; kx < 5; kx++)
                    a2 = fmaf(sw2[m*25 + ky*5 + kx], pc[yy + ((x + kx + 30) & 31)], a2);
            }
        }
        float e = expf(fw[0]*a1 + fw[1]*a2);
        g_eP [bp*HW + t]  = e;
        g_ePT[t*BP + bp]  = e;
    }
}

// ---------------- B transpose + premultiply: g_BT[bp][k][f] = feats*eP ------
__global__ __launch_bounds__(256) void k_BT(const float* __restrict__ feats) {
    __shared__ float s[32][132];
    int bp = blockIdx.x >> 3, kt = blockIdx.x & 7;
    int k0 = kt*32;
    int tid = threadIdx.x;
    int f = tid >> 1, kq = tid & 1;
    const float* fb = feats + ((size_t)bp*CC + f)*HW + k0 + kq*16;
    const float* ep = g_eP + (size_t)bp*HW + k0 + kq*16;
    #pragma unroll
    for (int q = 0; q < 4; q++) {
        float4 v = *(const float4*)(fb + q*4);
        float4 e = *(const float4*)(ep + q*4);
        int kl = kq*16 + q*4;
        s[kl+0][f] = v.x*e.x; s[kl+1][f] = v.y*e.y;
        s[kl+2][f] = v.z*e.z; s[kl+3][f] = v.w*e.w;
    }
    __syncthreads();
    #pragma unroll
    for (int q = 0; q < 4; q++) {
        int idx = q*256 + tid;
        int r = idx >> 5, cg = idx & 31;
        *(float4*)&g_BT[((size_t)bp*HW + k0 + r)*CC + cg*4] = *(float4*)&s[r][cg*4];
    }
}

// ---------------- T GEMM: T[ind,bp] = sum_hw eR[ind,hw]*eP[bp,hw] ----------
#define TTK 32
__global__ __launch_bounds__(256) void k_T() {
    __shared__ float sR[TTK][32];
    __shared__ float sP[TTK][BP];
    int ind0 = blockIdx.x * 32;
    int tid = threadIdx.x;
    int ti = tid & 31, gq = tid >> 5;
    float acc[10];
    #pragma unroll
    for (int j = 0; j < 10; j++) acc[j] = 0.f;

    for (int k0 = 0; k0 < HW; k0 += TTK) {
        {
            int kk = tid >> 3, q = tid & 7;
            *(float4*)&sR[kk][q*4] = *(const float4*)&g_eRT[(size_t)(k0+kk)*NI + ind0 + q*4];
        }
        for (int i = tid; i < TTK*(BP/4); i += 256) {
            int kk = i / (BP/4), q = i % (BP/4);
            *(float4*)&sP[kk][q*4] = *(const float4*)&g_ePT[(size_t)(k0+kk)*BP + q*4];
        }
        __syncthreads();
        #pragma unroll
        for (int kk = 0; kk < TTK; kk++) {
            float a = sR[kk][ti];
            #pragma unroll
            for (int j = 0; j < 10; j++)
                acc[j] = fmaf(a, sP[kk][gq*10 + j], acc[j]);
        }
        __syncthreads();
    }
    #pragma unroll
    for (int j = 0; j < 10; j++)
        g_T[(ind0 + ti)*BP + gq*10 + j] = acc[j];
}

// ---------------- geometry: warp per s-cell, lane per neighbor p ------------
__global__ __launch_bounds__(256) void k_geo(const float* __restrict__ bbox,
                                             const float* __restrict__ locs,
                                             const float* __restrict__ w1,
                                             const float* __restrict__ w2,
                                             const float* __restrict__ fw) {
    int b = blockIdx.y;
    int warp = threadIdx.x >> 5, lane = threadIdx.x & 31;
    int s = blockIdx.x * 8 + warp;

    // alpha: warp-parallel tap sums (conv1 ch0 = w1[0..8], conv2 ch0 = w2[0..24])
    float x1 = (lane < 9)  ? __ldg(w1 + lane) : 0.f;
    float x2 = (lane < 25) ? __ldg(w2 + lane) : 0.f;
    #pragma unroll
    for (int o = 16; o > 0; o >>= 1) {
        x1 += __shfl_xor_sync(0xffffffffu, x1, o);
        x2 += __shfl_xor_sync(0xffffffffu, x2, o);
    }
    float alpha = __ldg(fw) * x1 + __ldg(fw + 1) * x2;

    float sb0 = __ldg(bbox + b*4 + 0), sb1 = __ldg(bbox + b*4 + 1);
    float sb2 = __ldg(bbox + b*4 + 2), sb3 = __ldg(bbox + b*4 + 3);
    int iy = s >> 5, ix = s & 31;
    float ystep = __fdiv_rn(sb2 - sb0, 31.0f);
    float xstep = __fdiv_rn(sb3 - sb1, 31.0f);
    float py = __fadd_rn(sb0, __fmul_rn((float)iy, ystep));
    float px = __fadd_rn(sb1, __fmul_rn((float)ix, xstep));

    int p = (lane < NNB) ? lane : NNB-1;
    float ly = __ldg(locs + (b*NNB + p)*2);
    float lx = __ldg(locs + (b*NNB + p)*2 + 1);
    float dy = py - ly, dx = px - lx;
    float D = sqrtf(__fadd_rn(__fadd_rn(__fmul_rn(dy,dy), __fmul_rn(dx,dx)), 1e-12f));
    float th = atan2f(dx, dy);
    if (th < 0.f) th += 6.283185307179586f;
    float deg = __fmul_rn(th, 57.29577951308232f);
    int ind = (int)rintf(deg);
    if (ind >= 360) ind -= 360;
    float eD = expf(alpha * D);
    float Tv = __ldg(&g_T[ind*BP + b*NNB + p]);

    float z = (lane < NNB) ? eD * Tv : 0.f;
    #pragma unroll
    for (int o = 16; o > 0; o >>= 1)
        z += __shfl_xor_sync(0xffffffffu, z, o);

    int base = (b*LL + s)*NNB;
    if (lane < NNB) {
        g_ind[base + lane] = ind;
        g_eD [base + lane] = eD;
    }
    if (lane == 0) g_invZ[b*LL + s] = 1.0f / z;
}

// ---------------- G GEMM: cp.async double-buffered, 128x64, 8x4, FFMA2 ------
// G[bp, ind, f] = sum_k eRT[k][ind] * g_BT[bp][k][f]   (proven R10 version)
#define KC 32

#define MMA_ROW4(I, AV) do { unsigned long long pa_; \
    asm("mov.b64 %0, {%1, %1};" : "=l"(pa_) : "f"(AV)); \
    FMA_F32X2(acc[I][0], pa_, bA.x, acc[I][0]); \
    FMA_F32X2(acc[I][1], pa_, bA.y, acc[I][1]); } while(0)

__global__ __launch_bounds__(256, 4) void k_gemmG() {
    __shared__ __align__(16) float sA[2][KC][128];   // [k][m]: 1024 16B pieces
    __shared__ __align__(16) float sB[2][KC][64];    // [k][f]: 512 16B pieces
    const int m0 = blockIdx.x * 128;   // ind tile: 0,128,256
    const int n0 = blockIdx.y * 64;    // f tile: 0,64
    const int bp = blockIdx.z;
    int tid = threadIdx.x;
    int tx = tid & 15, ty = tid >> 4;

    // A: piece i = tid + q*256 -> row (tid>>5)+8q (0..31), col-piece tid&31.
    int ar0 = tid >> 5, acp = tid & 31;
    const float* aS = g_eRT + (size_t)ar0*NI + m0 + acp*4;
    uint32_t aD[2][4];
    #pragma unroll
    for (int q = 0; q < 4; q++) {
        aD[0][q] = smem_u32(&sA[0][ar0 + q*8][acp*4]);
        aD[1][q] = smem_u32(&sA[1][ar0 + q*8][acp*4]);
    }
    // B: 512 pieces, 2 per thread: idx = tid and tid+256
    int b0kk = tid >> 4, b0j = tid & 15;
    int b1kk = (tid + 256) >> 4;
    const float* b0S = g_BT + ((size_t)bp*HW + b0kk)*CC + n0 + b0j*4;
    const float* b1S = g_BT + ((size_t)bp*HW + b1kk)*CC + n0 + b0j*4;
    uint32_t b0D[2] = { smem_u32(&sB[0][b0kk][b0j*4]), smem_u32(&sB[1][b0kk][b0j*4]) };
    uint32_t b1D[2] = { smem_u32(&sB[0][b1kk][b0j*4]), smem_u32(&sB[1][b1kk][b0j*4]) };

    unsigned long long acc[8][2];
    #pragma unroll
    for (int i = 0; i < 8; i++) { acc[i][0] = 0ull; acc[i][1] = 0ull; }

    // prologue: chunk 0 into buffer 0
    #pragma unroll
    for (int q = 0; q < 4; q++) CP16(aD[0][q], aS + (size_t)q*8*NI);
    CP16(b0D[0], b0S); CP16(b1D[0], b1S);
    CP_COMMIT();

    #pragma unroll
    for (int c = 0; c < HW/KC; c++) {
        int buf = c & 1;
        CP_WAIT_ALL();
        __syncthreads();
        if (c < HW/KC - 1) {
            int nb = buf ^ 1;
            size_t ka = (size_t)(c+1)*KC*NI;
            size_t kb = (size_t)(c+1)*KC*CC;
            #pragma unroll
            for (int q = 0; q < 4; q++) CP16(aD[nb][q], aS + ka + (size_t)q*8*NI);
            CP16(b0D[nb], b0S + kb); CP16(b1D[nb], b1S + kb);
            CP_COMMIT();
        }
        #pragma unroll
        for (int kk = 0; kk < KC; kk++) {
            float4 av0 = *(const float4*)&sA[buf][kk][ty*8];
            float4 av1 = *(const float4*)&sA[buf][kk][ty*8 + 4];
            ulonglong2 bA = *(const ulonglong2*)&sB[buf][kk][tx*4];
            MMA_ROW4(0, av0.x); MMA_ROW4(1, av0.y);
            MMA_ROW4(2, av0.z); MMA_ROW4(3, av0.w);
            MMA_ROW4(4, av1.x); MMA_ROW4(5, av1.y);
            MMA_ROW4(6, av1.z); MMA_ROW4(7, av1.w);
        }
        __syncthreads();
    }

    float* gb = g_G + ((size_t)bp*NRAY + m0)*CC + n0 + tx*4;
    #pragma unroll
    for (int i = 0; i < 8; i++) {
        int m = ty*8 + i;
        if (m0 + m < NRAY) {
            float* row = gb + (size_t)m*CC;
            *(float2*)(row)     = *(float2*)&acc[i][0];
            *(float2*)(row + 2) = *(float2*)&acc[i][1];
        }
    }
}

// ---------------- merged outputs: grid_feats + attn ------------------------
__global__ void k_final(float* __restrict__ out) {
    int s = blockIdx.x, b = blockIdx.y, t = threadIdx.x;
    __shared__ int   si[NNB];
    __shared__ float se[NNB];
    __shared__ float sz;
    int base = (b*LL + s)*NNB;
    if (t < NNB) { si[t] = g_ind[base + t]; se[t] = g_eD[base + t]; }
    if (t == 0)  sz = g_invZ[b*LL + s];
    __syncthreads();
    float invZ = sz;
    if (t < CC) {
        float acc = 0.f;
        #pragma unroll
        for (int p = 0; p < NNB; p++)
            acc = fmaf(se[p], g_G[((size_t)(b*NNB + p)*NRAY + si[p])*CC + t], acc);
        out[(size_t)(b*LL + s)*CC + t] = acc * invZ;
    }
    float4* o = (float4*)(out + (size_t)BB*LL*CC + (size_t)base*HW);
    for (int i = t; i < NNB*(HW/4); i += 256) {
        int p = i >> 6, e = i & 63;
        float k = se[p] * invZ;
        float4 ep = ((const float4*)(g_eP + (size_t)(b*NNB + p)*HW))[e];
        float4 er = ((const float4*)(g_eR + (size_t)si[p]*HW))[e];
        o[i] = make_float4(k*ep.x*er.x, k*ep.y*er.y, k*ep.z*er.z, k*ep.w*er.w);
    }
}

// ---------------- launch -----------------------------------------------------
extern "C" void kernel_launch(void* const* d_in, const int* in_sizes, int n_in,
                              void* d_out, int out_size) {
    const float* bbox  = (const float*)d_in[0];
    const float* locs  = (const float*)d_in[1];
    const float* feats = (const float*)d_in[2];
    // d_in[3] = overhead_feat: cancels in the softmax -> unused
    const float* rays  = (const float*)d_in[4];
    const float* w1    = (const float*)d_in[5];
    const float* w2    = (const float*)d_in[7];
    const float* fw    = (const float*)d_in[9];
    float* out = (float*)d_out;

    k_RP<<<NRAY + BP, 256>>>(rays, feats, w1, w2, fw);
    k_BT<<<BP*8, 256>>>(feats);
    k_T<<<NI/32, 256>>>();
    dim3 gg2(LL/8, BB);
    k_geo<<<gg2, 256>>>(bbox, locs, w1, w2, fw);
    dim3 gg(3, 2, BP);
    k_gemmG<<<gg, 256>>>();
    dim3 go(LL, BB);
    k_final<<<go, 256>>>(out);
}

// round 15
// speedup vs baseline: 1.0019x; 1.0019x over previous
#include <cuda_runtime.h>
#include <math.h>
#include <stdint.h>

#define GSZ 32
#define LL  1024
#define BB  4
#define NNB 20
#define BP  (BB*NNB)     // 80
#define CC  128
#define HW  256
#define NRAY 360
#define NI   384

// packed f32x2 FMA (Blackwell): one inst = 2 fp32 FMAs
#define FMA_F32X2(d,a,b,c) asm("fma.rn.f32x2 %0, %1, %2, %3;" : "=l"(d) : "l"(a), "l"(b), "l"(c))
// cp.async 16B global->shared (L1 bypass)
#define CP16(dst, src) asm volatile("cp.async.cg.shared.global [%0], [%1], 16;" :: "r"(dst), "l"(src))
#define CP_COMMIT()    asm volatile("cp.async.commit_group;")
#define CP_WAIT_ALL()  asm volatile("cp.async.wait_group 0;")

__device__ __forceinline__ uint32_t smem_u32(const void* p) {
    uint32_t a;
    asm("{ .reg .u64 t; cvta.to.shared.u64 t, %1; cvt.u32.u64 %0, t; }" : "=r"(a) : "l"(p));
    return a;
}

// ---------------- scratch (device globals; no allocations) ----------------
__device__ float g_eR [NRAY*HW];
__device__ float g_eRT[HW*NI];            // [hw][ind], cols 360..383 stay zero
__device__ float g_eP [BP*HW];
__device__ float g_ePT[HW*BP];            // [hw][bp]
__device__ float g_BT [(size_t)BP*HW*CC]; // [bp][k][f] = feats*eP transposed
__device__ float g_T  [NI*BP];            // [ind][bp], rows >=360 garbage (never read)
__device__ float g_G[(size_t)BP*NRAY*CC]; // 14.7 MB
__device__ int   g_ind[BB*LL*NNB];
__device__ float g_eD [BB*LL*NNB];
__device__ float g_invZ[BB*LL];

// ---------------- merged R/P tables: circular convs + fused exp ------------
__global__ void k_RP(const float* __restrict__ rays, const float* __restrict__ feats,
                     const float* __restrict__ w1, const float* __restrict__ w2,
                     const float* __restrict__ fw) {
    __shared__ float sbuf[3*HW];
    __shared__ float sw1[27], sw2[75];
    int t = threadIdx.x;
    int y = t >> 5, x = t & 31;

    if (blockIdx.x < NRAY) {
        int ind = blockIdx.x;
        for (int i = t; i < 3*HW; i += 256) sbuf[i] = rays[(size_t)ind*3*HW + i];
        if (t < 27) sw1[t] = w1[9  + t];   // conv1 channels 1..3
        if (t < 75) sw2[t] = w2[25 + t];   // conv2 channels 1..3
        __syncthreads();
        float a1 = 0.f, a2 = 0.f;
        #pragma unroll
        for (int c = 0; c < 3; c++) {
            const float* rc = sbuf + c*HW;
            #pragma unroll
            for (int ky = 0; ky < 3; ky++) {
                int yy = ((y + ky + 7) & 7) * 32;
                #pragma unroll
                for (int kx = 0; kx < 3; kx++)
                    a1 = fmaf(sw1[c*9 + ky*3 + kx], rc[yy + ((x + kx + 31) & 31)], a1);
            }
            #pragma unroll
            for (int ky = 0; ky < 5; ky++) {
                int yy = ((y + ky + 6) & 7) * 32;
                #pragma unroll
                for (int kx = 0; kx < 5; kx++)
                    a2 = fmaf(sw2[c*25 + ky*5 + kx], rc[yy + ((x + kx + 30) & 31)], a2);
            }
        }
        float e = expf(fw[0]*a1 + fw[1]*a2);
        g_eR [ind*HW + t]  = e;
        g_eRT[t*NI + ind]  = e;
    } else {
        int bp = blockIdx.x - NRAY;
        {
            const float* base = feats + (size_t)bp*CC*HW + t;
            float mx = -3.4e38f, sm = 0.f;
            #pragma unroll 8
            for (int c = 0; c < CC; c++) {
                float v = base[(size_t)c*HW];
                mx = fmaxf(mx, v);
                sm += v;
            }
            sbuf[t]      = mx;
            sbuf[HW + t] = sm * (1.0f/128.0f);
        }
        if (t < 18) sw1[t] = w1[4*9  + t];  // conv1 channels 4..5
        if (t < 50) sw2[t] = w2[4*25 + t];  // conv2 channels 4..5
        __syncthreads();
        float a1 = 0.f, a2 = 0.f;
        #pragma unroll
        for (int m = 0; m < 2; m++) {
            const float* pc = sbuf + m*HW;
            #pragma unroll
            for (int ky = 0; ky < 3; ky++) {
                int yy = ((y + ky + 7) & 7) * 32;
                #pragma unroll
                for (int kx = 0; kx < 3; kx++)
                    a1 = fmaf(sw1[m*9 + ky*3 + kx], pc[yy + ((x + kx + 31) & 31)], a1);
            }
            #pragma unroll
            for (int ky = 0; ky < 5; ky++) {
                int yy = ((y + ky + 6) & 7) * 32;
                #pragma unroll
                for (int kx = 0; kx < 5; kx++)
                    a2 = fmaf(sw2[m*25 + ky*5 + kx], pc[yy + ((x + kx + 30) & 31)], a2);
            }
        }
        float e = expf(fw[0]*a1 + fw[1]*a2);
        g_eP [bp*HW + t]  = e;
        g_ePT[t*BP + bp]  = e;
    }
}

// ---------------- B transpose + premultiply: g_BT[bp][k][f] = feats*eP ------
__global__ __launch_bounds__(256) void k_BT(const float* __restrict__ feats) {
    __shared__ float s[32][132];
    int bp = blockIdx.x >> 3, kt = blockIdx.x & 7;
    int k0 = kt*32;
    int tid = threadIdx.x;
    int f = tid >> 1, kq = tid & 1;
    const float* fb = feats + ((size_t)bp*CC + f)*HW + k0 + kq*16;
    const float* ep = g_eP + (size_t)bp*HW + k0 + kq*16;
    #pragma unroll
    for (int q = 0; q < 4; q++) {
        float4 v = *(const float4*)(fb + q*4);
        float4 e = *(const float4*)(ep + q*4);
        int kl = kq*16 + q*4;
        s[kl+0][f] = v.x*e.x; s[kl+1][f] = v.y*e.y;
        s[kl+2][f] = v.z*e.z; s[kl+3][f] = v.w*e.w;
    }
    __syncthreads();
    #pragma unroll
    for (int q = 0; q < 4; q++) {
        int idx = q*256 + tid;
        int r = idx >> 5, cg = idx & 31;
        *(float4*)&g_BT[((size_t)bp*HW + k0 + r)*CC + cg*4] = *(float4*)&s[r][cg*4];
    }
}

// ---------------- T GEMM: T[ind,bp] = sum_hw eR[ind,hw]*eP[bp,hw] ----------
#define TTK 32
__global__ __launch_bounds__(256) void k_T() {
    __shared__ float sR[TTK][32];
    __shared__ float sP[TTK][BP];
    int ind0 = blockIdx.x * 32;
    int tid = threadIdx.x;
    int ti = tid & 31, gq = tid >> 5;
    float acc[10];
    #pragma unroll
    for (int j = 0; j < 10; j++) acc[j] = 0.f;

    for (int k0 = 0; k0 < HW; k0 += TTK) {
        {
            int kk = tid >> 3, q = tid & 7;
            *(float4*)&sR[kk][q*4] = *(const float4*)&g_eRT[(size_t)(k0+kk)*NI + ind0 + q*4];
        }
        for (int i = tid; i < TTK*(BP/4); i += 256) {
            int kk = i / (BP/4), q = i % (BP/4);
            *(float4*)&sP[kk][q*4] = *(const float4*)&g_ePT[(size_t)(k0+kk)*BP + q*4];
        }
        __syncthreads();
        #pragma unroll
        for (int kk = 0; kk < TTK; kk++) {
            float a = sR[kk][ti];
            #pragma unroll
            for (int j = 0; j < 10; j++)
                acc[j] = fmaf(a, sP[kk][gq*10 + j], acc[j]);
        }
        __syncthreads();
    }
    #pragma unroll
    for (int j = 0; j < 10; j++)
        g_T[(ind0 + ti)*BP + gq*10 + j] = acc[j];
}

// ---------------- geometry: warp per s-cell, lane per neighbor p ------------
__global__ __launch_bounds__(256) void k_geo(const float* __restrict__ bbox,
                                             const float* __restrict__ locs,
                                             const float* __restrict__ w1,
                                             const float* __restrict__ w2,
                                             const float* __restrict__ fw) {
    int b = blockIdx.y;
    int warp = threadIdx.x >> 5, lane = threadIdx.x & 31;
    int s = blockIdx.x * 8 + warp;

    // alpha: warp-parallel tap sums (conv1 ch0 = w1[0..8], conv2 ch0 = w2[0..24])
    float x1 = (lane < 9)  ? __ldg(w1 + lane) : 0.f;
    float x2 = (lane < 25) ? __ldg(w2 + lane) : 0.f;
    #pragma unroll
    for (int o = 16; o > 0; o >>= 1) {
        x1 += __shfl_xor_sync(0xffffffffu, x1, o);
        x2 += __shfl_xor_sync(0xffffffffu, x2, o);
    }
    float alpha = __ldg(fw) * x1 + __ldg(fw + 1) * x2;

    float sb0 = __ldg(bbox + b*4 + 0), sb1 = __ldg(bbox + b*4 + 1);
    float sb2 = __ldg(bbox + b*4 + 2), sb3 = __ldg(bbox + b*4 + 3);
    int iy = s >> 5, ix = s & 31;
    float ystep = __fdiv_rn(sb2 - sb0, 31.0f);
    float xstep = __fdiv_rn(sb3 - sb1, 31.0f);
    float py = __fadd_rn(sb0, __fmul_rn((float)iy, ystep));
    float px = __fadd_rn(sb1, __fmul_rn((float)ix, xstep));

    int p = (lane < NNB) ? lane : NNB-1;
    float ly = __ldg(locs + (b*NNB + p)*2);
    float lx = __ldg(locs + (b*NNB + p)*2 + 1);
    float dy = py - ly, dx = px - lx;
    float D = sqrtf(__fadd_rn(__fadd_rn(__fmul_rn(dy,dy), __fmul_rn(dx,dx)), 1e-12f));
    float th = atan2f(dx, dy);
    if (th < 0.f) th += 6.283185307179586f;
    float deg = __fmul_rn(th, 57.29577951308232f);
    int ind = (int)rintf(deg);
    if (ind >= 360) ind -= 360;
    float eD = expf(alpha * D);
    float Tv = __ldg(&g_T[ind*BP + b*NNB + p]);

    float z = (lane < NNB) ? eD * Tv : 0.f;
    #pragma unroll
    for (int o = 16; o > 0; o >>= 1)
        z += __shfl_xor_sync(0xffffffffu, z, o);

    int base = (b*LL + s)*NNB;
    if (lane < NNB) {
        g_ind[base + lane] = ind;
        g_eD [base + lane] = eD;
    }
    if (lane == 0) g_invZ[b*LL + s] = 1.0f / z;
}

// ---------------- G GEMM: cp.async double-buffered, 128x64, 8x4, FFMA2 ------
// G[bp, ind, f] = sum_k eRT[k][ind] * g_BT[bp][k][f]   (proven R10 version)
#define KC 32

#define MMA_ROW4(I, AV) do { unsigned long long pa_; \
    asm("mov.b64 %0, {%1, %1};" : "=l"(pa_) : "f"(AV)); \
    FMA_F32X2(acc[I][0], pa_, bA.x, acc[I][0]); \
    FMA_F32X2(acc[I][1], pa_, bA.y, acc[I][1]); } while(0)

__global__ __launch_bounds__(256, 4) void k_gemmG() {
    __shared__ __align__(16) float sA[2][KC][128];   // [k][m]: 1024 16B pieces
    __shared__ __align__(16) float sB[2][KC][64];    // [k][f]: 512 16B pieces
    const int m0 = blockIdx.x * 128;   // ind tile: 0,128,256
    const int n0 = blockIdx.y * 64;    // f tile: 0,64
    const int bp = blockIdx.z;
    int tid = threadIdx.x;
    int tx = tid & 15, ty = tid >> 4;

    // A: piece i = tid + q*256 -> row (tid>>5)+8q (0..31), col-piece tid&31.
    int ar0 = tid >> 5, acp = tid & 31;
    const float* aS = g_eRT + (size_t)ar0*NI + m0 + acp*4;
    uint32_t aD[2][4];
    #pragma unroll
    for (int q = 0; q < 4; q++) {
        aD[0][q] = smem_u32(&sA[0][ar0 + q*8][acp*4]);
        aD[1][q] = smem_u32(&sA[1][ar0 + q*8][acp*4]);
    }
    // B: 512 pieces, 2 per thread: idx = tid and tid+256
    int b0kk = tid >> 4, b0j = tid & 15;
    int b1kk = (tid + 256) >> 4;
    const float* b0S = g_BT + ((size_t)bp*HW + b0kk)*CC + n0 + b0j*4;
    const float* b1S = g_BT + ((size_t)bp*HW + b1kk)*CC + n0 + b0j*4;
    uint32_t b0D[2] = { smem_u32(&sB[0][b0kk][b0j*4]), smem_u32(&sB[1][b0kk][b0j*4]) };
    uint32_t b1D[2] = { smem_u32(&sB[0][b1kk][b0j*4]), smem_u32(&sB[1][b1kk][b0j*4]) };

    unsigned long long acc[8][2];
    #pragma unroll
    for (int i = 0; i < 8; i++) { acc[i][0] = 0ull; acc[i][1] = 0ull; }

    // prologue: chunk 0 into buffer 0
    #pragma unroll
    for (int q = 0; q < 4; q++) CP16(aD[0][q], aS + (size_t)q*8*NI);
    CP16(b0D[0], b0S); CP16(b1D[0], b1S);
    CP_COMMIT();

    #pragma unroll
    for (int c = 0; c < HW/KC; c++) {
        int buf = c & 1;
        CP_WAIT_ALL();
        __syncthreads();
        if (c < HW/KC - 1) {
            int nb = buf ^ 1;
            size_t ka = (size_t)(c+1)*KC*NI;
            size_t kb = (size_t)(c+1)*KC*CC;
            #pragma unroll
            for (int q = 0; q < 4; q++) CP16(aD[nb][q], aS + ka + (size_t)q*8*NI);
            CP16(b0D[nb], b0S + kb); CP16(b1D[nb], b1S + kb);
            CP_COMMIT();
        }
        #pragma unroll
        for (int kk = 0; kk < KC; kk++) {
            float4 av0 = *(const float4*)&sA[buf][kk][ty*8];
            float4 av1 = *(const float4*)&sA[buf][kk][ty*8 + 4];
            ulonglong2 bA = *(const ulonglong2*)&sB[buf][kk][tx*4];
            MMA_ROW4(0, av0.x); MMA_ROW4(1, av0.y);
            MMA_ROW4(2, av0.z); MMA_ROW4(3, av0.w);
            MMA_ROW4(4, av1.x); MMA_ROW4(5, av1.y);
            MMA_ROW4(6, av1.z); MMA_ROW4(7, av1.w);
        }
        __syncthreads();
    }

    float* gb = g_G + ((size_t)bp*NRAY + m0)*CC + n0 + tx*4;
    #pragma unroll
    for (int i = 0; i < 8; i++) {
        int m = ty*8 + i;
        if (m0 + m < NRAY) {
            float* row = gb + (size_t)m*CC;
            *(float2*)(row)     = *(float2*)&acc[i][0];
            *(float2*)(row + 2) = *(float2*)&acc[i][1];
        }
    }
}

// ---------------- merged outputs: grid_feats + attn ------------------------
__global__ void k_final(float* __restrict__ out) {
    int s = blockIdx.x, b = blockIdx.y, t = threadIdx.x;
    __shared__ int   si[NNB];
    __shared__ float se[NNB];
    __shared__ float sz;
    int base = (b*LL + s)*NNB;
    if (t < NNB) { si[t] = g_ind[base + t]; se[t] = g_eD[base + t]; }
    if (t == 0)  sz = g_invZ[b*LL + s];
    __syncthreads();
    float invZ = sz;
    if (t < CC) {
        float acc = 0.f;
        #pragma unroll
        for (int p = 0; p < NNB; p++)
            acc = fmaf(se[p], g_G[((size_t)(b*NNB + p)*NRAY + si[p])*CC + t], acc);
        out[(size_t)(b*LL + s)*CC + t] = acc * invZ;
    }
    float4* o = (float4*)(out + (size_t)BB*LL*CC + (size_t)base*HW);
    for (int i = t; i < NNB*(HW/4); i += 256) {
        int p = i >> 6, e = i & 63;
        float k = se[p] * invZ;
        float4 ep = ((const float4*)(g_eP + (size_t)(b*NNB + p)*HW))[e];
        float4 er = ((const float4*)(g_eR + (size_t)si[p]*HW))[e];
        o[i] = make_float4(k*ep.x*er.x, k*ep.y*er.y, k*ep.z*er.z, k*ep.w*er.w);
    }
}

// ---------------- launch -----------------------------------------------------
extern "C" void kernel_launch(void* const* d_in, const int* in_sizes, int n_in,
                              void* d_out, int out_size) {
    const float* bbox  = (const float*)d_in[0];
    const float* locs  = (const float*)d_in[1];
    const float* feats = (const float*)d_in[2];
    // d_in[3] = overhead_feat: cancels in the softmax -> unused
    const float* rays  = (const float*)d_in[4];
    const float* w1    = (const float*)d_in[5];
    const float* w2    = (const float*)d_in[7];
    const float* fw    = (const float*)d_in[9];
    float* out = (float*)d_out;

    k_RP<<<NRAY + BP, 256>>>(rays, feats, w1, w2, fw);
    k_BT<<<BP*8, 256>>>(feats);
    k_T<<<NI/32, 256>>>();
    dim3 gg2(LL/8, BB);
    k_geo<<<gg2, 256>>>(bbox, locs, w1, w2, fw);
    dim3 gg(3, 2, BP);
    k_gemmG<<<gg, 256>>>();
    dim3 go(LL, BB);
    k_final<<<go, 256>>>(out);
}

// round 16
// speedup vs baseline: 1.0074x; 1.0055x over previous
#include <cuda_runtime.h>
#include <math.h>
#include <stdint.h>

#define GSZ 32
#define LL  1024
#define BB  4
#define NNB 20
#define BP  (BB*NNB)     // 80
#define CC  128
#define HW  256
#define NRAY 360
#define NI   384

// packed f32x2 FMA (Blackwell): one inst = 2 fp32 FMAs
#define FMA_F32X2(d,a,b,c) asm("fma.rn.f32x2 %0, %1, %2, %3;" : "=l"(d) : "l"(a), "l"(b), "l"(c))
// cp.async 16B global->shared (L1 bypass)
#define CP16(dst, src) asm volatile("cp.async.cg.shared.global [%0], [%1], 16;" :: "r"(dst), "l"(src))
#define CP_COMMIT()    asm volatile("cp.async.commit_group;")
#define CP_WAIT_ALL()  asm volatile("cp.async.wait_group 0;")

__device__ __forceinline__ uint32_t smem_u32(const void* p) {
    uint32_t a;
    asm("{ .reg .u64 t; cvta.to.shared.u64 t, %1; cvt.u32.u64 %0, t; }" : "=r"(a) : "l"(p));
    return a;
}

// ---------------- scratch (device globals; no allocations) ----------------
__device__ float g_eR [NRAY*HW];
__device__ float g_eRT[HW*NI];            // [hw][ind], cols 360..383 stay zero
__device__ float g_eP [BP*HW];
__device__ float g_ePT[HW*BP];            // [hw][bp]
__device__ float g_BT [(size_t)BP*HW*CC]; // [bp][k][f] = feats*eP transposed
__device__ float g_T  [NI*BP];            // [ind][bp], rows >=360 garbage (never read)
__device__ float g_G[(size_t)BP*NRAY*CC]; // 14.7 MB
__device__ int   g_ind[BB*LL*NNB];
__device__ float g_eD [BB*LL*NNB];
__device__ float g_invZ[BB*LL];

// ---------------- merged R/P tables: circular convs + fused exp ------------
__global__ void k_RP(const float* __restrict__ rays, const float* __restrict__ feats,
                     const float* __restrict__ w1, const float* __restrict__ w2,
                     const float* __restrict__ fw) {
    __shared__ float sbuf[3*HW];
    __shared__ float sw1[27], sw2[75];
    int t = threadIdx.x;
    int y = t >> 5, x = t & 31;

    if (blockIdx.x < NRAY) {
        int ind = blockIdx.x;
        for (int i = t; i < 3*HW; i += 256) sbuf[i] = rays[(size_t)ind*3*HW + i];
        if (t < 27) sw1[t] = w1[9  + t];   // conv1 channels 1..3
        if (t < 75) sw2[t] = w2[25 + t];   // conv2 channels 1..3
        __syncthreads();
        float a1 = 0.f, a2 = 0.f;
        #pragma unroll
        for (int c = 0; c < 3; c++) {
            const float* rc = sbuf + c*HW;
            #pragma unroll
            for (int ky = 0; ky < 3; ky++) {
                int yy = ((y + ky + 7) & 7) * 32;
                #pragma unroll
                for (int kx = 0; kx < 3; kx++)
                    a1 = fmaf(sw1[c*9 + ky*3 + kx], rc[yy + ((x + kx + 31) & 31)], a1);
            }
            #pragma unroll
            for (int ky = 0; ky < 5; ky++) {
                int yy = ((y + ky + 6) & 7) * 32;
                #pragma unroll
                for (int kx = 0; kx < 5; kx++)
                    a2 = fmaf(sw2[c*25 + ky*5 + kx], rc[yy + ((x + kx + 30) & 31)], a2);
            }
        }
        float e = expf(fw[0]*a1 + fw[1]*a2);
        g_eR [ind*HW + t]  = e;
        g_eRT[t*NI + ind]  = e;
    } else {
        int bp = blockIdx.x - NRAY;
        {
            const float* base = feats + (size_t)bp*CC*HW + t;
            float mx = -3.4e38f, sm = 0.f;
            #pragma unroll 8
            for (int c = 0; c < CC; c++) {
                float v = base[(size_t)c*HW];
                mx = fmaxf(mx, v);
                sm += v;
            }
            sbuf[t]      = mx;
            sbuf[HW + t] = sm * (1.0f/128.0f);
        }
        if (t < 18) sw1[t] = w1[4*9  + t];  // conv1 channels 4..5
        if (t < 50) sw2[t] = w2[4*25 + t];  // conv2 channels 4..5
        __syncthreads();
        float a1 = 0.f, a2 = 0.f;
        #pragma unroll
        for (int m = 0; m < 2; m++) {
            const float* pc = sbuf + m*HW;
            #pragma unroll
            for (int ky = 0; ky < 3; ky++) {
                int yy = ((y + ky + 7) & 7) * 32;
                #pragma unroll
                for (int kx = 0; kx < 3; kx++)
                    a1 = fmaf(sw1[m*9 + ky*3 + kx], pc[yy + ((x + kx + 31) & 31)], a1);
            }
            #pragma unroll
            for (int ky = 0; ky < 5; ky++) {
                int yy = ((y + ky + 6) & 7) * 32;
                #pragma unroll
                for (int kx = 0; kx < 5; kx++)
                    a2 = fmaf(sw2[m*25 + ky*5 + kx], pc[yy + ((x + kx + 30) & 31)], a2);
            }
        }
        float e = expf(fw[0]*a1 + fw[1]*a2);
        g_eP [bp*HW + t]  = e;
        g_ePT[t*BP + bp]  = e;
    }
}

// ---------------- B transpose + premultiply: g_BT[bp][k][f] = feats*eP ------
__global__ __launch_bounds__(256) void k_BT(const float* __restrict__ feats) {
    __shared__ float s[32][132];
    int bp = blockIdx.x >> 3, kt = blockIdx.x & 7;
    int k0 = kt*32;
    int tid = threadIdx.x;
    int f = tid >> 1, kq = tid & 1;
    const float* fb = feats + ((size_t)bp*CC + f)*HW + k0 + kq*16;
    const float* ep = g_eP + (size_t)bp*HW + k0 + kq*16;
    #pragma unroll
    for (int q = 0; q < 4; q++) {
        float4 v = *(const float4*)(fb + q*4);
        float4 e = *(const float4*)(ep + q*4);
        int kl = kq*16 + q*4;
        s[kl+0][f] = v.x*e.x; s[kl+1][f] = v.y*e.y;
        s[kl+2][f] = v.z*e.z; s[kl+3][f] = v.w*e.w;
    }
    __syncthreads();
    #pragma unroll
    for (int q = 0; q < 4; q++) {
        int idx = q*256 + tid;
        int r = idx >> 5, cg = idx & 31;
        *(float4*)&g_BT[((size_t)bp*HW + k0 + r)*CC + cg*4] = *(float4*)&s[r][cg*4];
    }
}

// ---------------- T GEMM: T[ind,bp] = sum_hw eR[ind,hw]*eP[bp,hw] ----------
#define TTK 32
__global__ __launch_bounds__(256) void k_T() {
    __shared__ float sR[TTK][32];
    __shared__ float sP[TTK][BP];
    int ind0 = blockIdx.x * 32;
    int tid = threadIdx.x;
    int ti = tid & 31, gq = tid >> 5;
    float acc[10];
    #pragma unroll
    for (int j = 0; j < 10; j++) acc[j] = 0.f;

    for (int k0 = 0; k0 < HW; k0 += TTK) {
        {
            int kk = tid >> 3, q = tid & 7;
            *(float4*)&sR[kk][q*4] = *(const float4*)&g_eRT[(size_t)(k0+kk)*NI + ind0 + q*4];
        }
        for (int i = tid; i < TTK*(BP/4); i += 256) {
            int kk = i / (BP/4), q = i % (BP/4);
            *(float4*)&sP[kk][q*4] = *(const float4*)&g_ePT[(size_t)(k0+kk)*BP + q*4];
        }
        __syncthreads();
        #pragma unroll
        for (int kk = 0; kk < TTK; kk++) {
            float a = sR[kk][ti];
            #pragma unroll
            for (int j = 0; j < 10; j++)
                acc[j] = fmaf(a, sP[kk][gq*10 + j], acc[j]);
        }
        __syncthreads();
    }
    #pragma unroll
    for (int j = 0; j < 10; j++)
        g_T[(ind0 + ti)*BP + gq*10 + j] = acc[j];
}

// ---------------- geometry: warp per s-cell, lane per neighbor p ------------
__global__ __launch_bounds__(256) void k_geo(const float* __restrict__ bbox,
                                             const float* __restrict__ locs,
                                             const float* __restrict__ w1,
                                             const float* __restrict__ w2,
                                             const float* __restrict__ fw) {
    int b = blockIdx.y;
    int warp = threadIdx.x >> 5, lane = threadIdx.x & 31;
    int s = blockIdx.x * 8 + warp;

    // alpha: warp-parallel tap sums (conv1 ch0 = w1[0..8], conv2 ch0 = w2[0..24])
    float x1 = (lane < 9)  ? __ldg(w1 + lane) : 0.f;
    float x2 = (lane < 25) ? __ldg(w2 + lane) : 0.f;
    #pragma unroll
    for (int o = 16; o > 0; o >>= 1) {
        x1 += __shfl_xor_sync(0xffffffffu, x1, o);
        x2 += __shfl_xor_sync(0xffffffffu, x2, o);
    }
    float alpha = __ldg(fw) * x1 + __ldg(fw + 1) * x2;

    float sb0 = __ldg(bbox + b*4 + 0), sb1 = __ldg(bbox + b*4 + 1);
    float sb2 = __ldg(bbox + b*4 + 2), sb3 = __ldg(bbox + b*4 + 3);
    int iy = s >> 5, ix = s & 31;
    float ystep = __fdiv_rn(sb2 - sb0, 31.0f);
    float xstep = __fdiv_rn(sb3 - sb1, 31.0f);
    float py = __fadd_rn(sb0, __fmul_rn((float)iy, ystep));
    float px = __fadd_rn(sb1, __fmul_rn((float)ix, xstep));

    int p = (lane < NNB) ? lane : NNB-1;
    float ly = __ldg(locs + (b*NNB + p)*2);
    float lx = __ldg(locs + (b*NNB + p)*2 + 1);
    float dy = py - ly, dx = px - lx;
    float D = sqrtf(__fadd_rn(__fadd_rn(__fmul_rn(dy,dy), __fmul_rn(dx,dx)), 1e-12f));
    float th = atan2f(dx, dy);
    if (th < 0.f) th += 6.283185307179586f;
    float deg = __fmul_rn(th, 57.29577951308232f);
    int ind = (int)rintf(deg);
    if (ind >= 360) ind -= 360;
    float eD = expf(alpha * D);
    float Tv = __ldg(&g_T[ind*BP + b*NNB + p]);

    float z = (lane < NNB) ? eD * Tv : 0.f;
    #pragma unroll
    for (int o = 16; o > 0; o >>= 1)
        z += __shfl_xor_sync(0xffffffffu, z, o);

    int base = (b*LL + s)*NNB;
    if (lane < NNB) {
        g_ind[base + lane] = ind;
        g_eD [base + lane] = eD;
    }
    if (lane == 0) g_invZ[b*LL + s] = 1.0f / z;
}

// ---------------- G GEMM: cp.async double-buffered, 128x64, 8x4, FFMA2 ------
// G[bp, ind, f] = sum_k eRT[k][ind] * g_BT[bp][k][f]   (proven R10 version)
#define KC 32

#define MMA_ROW4(I, AV) do { unsigned long long pa_; \
    asm("mov.b64 %0, {%1, %1};" : "=l"(pa_) : "f"(AV)); \
    FMA_F32X2(acc[I][0], pa_, bA.x, acc[I][0]); \
    FMA_F32X2(acc[I][1], pa_, bA.y, acc[I][1]); } while(0)

__global__ __launch_bounds__(256, 4) void k_gemmG() {
    __shared__ __align__(16) float sA[2][KC][128];   // [k][m]: 1024 16B pieces
    __shared__ __align__(16) float sB[2][KC][64];    // [k][f]: 512 16B pieces
    const int m0 = blockIdx.x * 128;   // ind tile: 0,128,256
    const int n0 = blockIdx.y * 64;    // f tile: 0,64
    const int bp = blockIdx.z;
    int tid = threadIdx.x;
    int tx = tid & 15, ty = tid >> 4;

    // A: piece i = tid + q*256 -> row (tid>>5)+8q (0..31), col-piece tid&31.
    int ar0 = tid >> 5, acp = tid & 31;
    const float* aS = g_eRT + (size_t)ar0*NI + m0 + acp*4;
    uint32_t aD[2][4];
    #pragma unroll
    for (int q = 0; q < 4; q++) {
        aD[0][q] = smem_u32(&sA[0][ar0 + q*8][acp*4]);
        aD[1][q] = smem_u32(&sA[1][ar0 + q*8][acp*4]);
    }
    // B: 512 pieces, 2 per thread: idx = tid and tid+256
    int b0kk = tid >> 4, b0j = tid & 15;
    int b1kk = (tid + 256) >> 4;
    const float* b0S = g_BT + ((size_t)bp*HW + b0kk)*CC + n0 + b0j*4;
    const float* b1S = g_BT + ((size_t)bp*HW + b1kk)*CC + n0 + b0j*4;
    uint32_t b0D[2] = { smem_u32(&sB[0][b0kk][b0j*4]), smem_u32(&sB[1][b0kk][b0j*4]) };
    uint32_t b1D[2] = { smem_u32(&sB[0][b1kk][b0j*4]), smem_u32(&sB[1][b1kk][b0j*4]) };

    unsigned long long acc[8][2];
    #pragma unroll
    for (int i = 0; i < 8; i++) { acc[i][0] = 0ull; acc[i][1] = 0ull; }

    // prologue: chunk 0 into buffer 0
    #pragma unroll
    for (int q = 0; q < 4; q++) CP16(aD[0][q], aS + (size_t)q*8*NI);
    CP16(b0D[0], b0S); CP16(b1D[0], b1S);
    CP_COMMIT();

    #pragma unroll
    for (int c = 0; c < HW/KC; c++) {
        int buf = c & 1;
        CP_WAIT_ALL();
        __syncthreads();
        if (c < HW/KC - 1) {
            int nb = buf ^ 1;
            size_t ka = (size_t)(c+1)*KC*NI;
            size_t kb = (size_t)(c+1)*KC*CC;
            #pragma unroll
            for (int q = 0; q < 4; q++) CP16(aD[nb][q], aS + ka + (size_t)q*8*NI);
            CP16(b0D[nb], b0S + kb); CP16(b1D[nb], b1S + kb);
            CP_COMMIT();
        }
        #pragma unroll
        for (int kk = 0; kk < KC; kk++) {
            float4 av0 = *(const float4*)&sA[buf][kk][ty*8];
            float4 av1 = *(const float4*)&sA[buf][kk][ty*8 + 4];
            ulonglong2 bA = *(const ulonglong2*)&sB[buf][kk][tx*4];
            MMA_ROW4(0, av0.x); MMA_ROW4(1, av0.y);
            MMA_ROW4(2, av0.z); MMA_ROW4(3, av0.w);
            MMA_ROW4(4, av1.x); MMA_ROW4(5, av1.y);
            MMA_ROW4(6, av1.z); MMA_ROW4(7, av1.w);
        }
        __syncthreads();
    }

    float* gb = g_G + ((size_t)bp*NRAY + m0)*CC + n0 + tx*4;
    #pragma unroll
    for (int i = 0; i < 8; i++) {
        int m = ty*8 + i;
        if (m0 + m < NRAY) {
            float* row = gb + (size_t)m*CC;
            *(float2*)(row)     = *(float2*)&acc[i][0];
            *(float2*)(row + 2) = *(float2*)&acc[i][1];
        }
    }
}

// ---------------- merged outputs: grid_feats + attn ------------------------
__global__ void k_final(float* __restrict__ out) {
    int s = blockIdx.x, b = blockIdx.y, t = threadIdx.x;
    __shared__ int   si[NNB];
    __shared__ float se[NNB];
    __shared__ float sz;
    int base = (b*LL + s)*NNB;
    if (t < NNB) { si[t] = g_ind[base + t]; se[t] = g_eD[base + t]; }
    if (t == 0)  sz = g_invZ[b*LL + s];
    __syncthreads();
    float invZ = sz;
    if (t < CC) {
        float acc = 0.f;
        #pragma unroll
        for (int p = 0; p < NNB; p++)
            acc = fmaf(se[p], g_G[((size_t)(b*NNB + p)*NRAY + si[p])*CC + t], acc);
        out[(size_t)(b*LL + s)*CC + t] = acc * invZ;
    }
    float4* o = (float4*)(out + (size_t)BB*LL*CC + (size_t)base*HW);
    for (int i = t; i < NNB*(HW/4); i += 256) {
        int p = i >> 6, e = i & 63;
        float k = se[p] * invZ;
        float4 ep = ((const float4*)(g_eP + (size_t)(b*NNB + p)*HW))[e];
        float4 er = ((const float4*)(g_eR + (size_t)si[p]*HW))[e];
        o[i] = make_float4(k*ep.x*er.x, k*ep.y*er.y, k*ep.z*er.z, k*ep.w*er.w);
    }
}

// ---------------- launch -----------------------------------------------------
extern "C" void kernel_launch(void* const* d_in, const int* in_sizes, int n_in,
                              void* d_out, int out_size) {
    const float* bbox  = (const float*)d_in[0];
    const float* locs  = (const float*)d_in[1];
    const float* feats = (const float*)d_in[2];
    // d_in[3] = overhead_feat: cancels in the softmax -> unused
    const float* rays  = (const float*)d_in[4];
    const float* w1    = (const float*)d_in[5];
    const float* w2    = (const float*)d_in[7];
    const float* fw    = (const float*)d_in[9];
    float* out = (float*)d_out;

    k_RP<<<NRAY + BP, 256>>>(rays, feats, w1, w2, fw);
    k_BT<<<BP*8, 256>>>(feats);
    k_T<<<NI/32, 256>>>();
    dim3 gg2(LL/8, BB);
    k_geo<<<gg2, 256>>>(bbox, locs, w1, w2, fw);
    dim3 gg(3, 2, BP);
    k_gemmG<<<gg, 256>>>();
    dim3 go(LL, BB);
    k_final<<<go, 256>>>(out);
}